// round 16
// baseline (speedup 1.0000x reference)
#include <cuda_runtime.h>
#include <cuda_fp16.h>
#include <math.h>
#include <stdint.h>

#define LYR 6
#define BB  16
#define HH  384
#define TT  2048
#define N2  32
#define HF  1536
#define NTOK (BB*TT)

// ---------------- scratch (device globals) ----------------------------------------
__device__ float g_a[(size_t)NTOK*HH];   // xcur [B,T,H]
__device__ float g_b[(size_t)NTOK*HH];   // s4 / FFN out
__device__ float g_c[(size_t)NTOK*HH];   // x1 (LN1 out)
__device__ __half g_xt[(size_t)NTOK*HH];  // fp16 K=384 operand [B,T,H]
__device__ __half g_ht[(size_t)NTOK*HF];  // fp16 K=1536 operand [B,T,HF]
__device__ __half g_woutt[LYR*2*HH*HH];   // GLU-permuted, fragment-packed fp16 weights
__device__ __half g_w1t[LYR*HF*HH];
__device__ __half g_w2t[LYR*HH*HF];

// ================= helpers =================
__device__ __forceinline__ uint32_t smem_u32(const void* p) {
    uint32_t a;
    asm("{ .reg .u64 t; cvta.to.shared.u64 t, %1; cvt.u32.u64 %0, t; }" : "=r"(a) : "l"(p));
    return a;
}
__device__ __forceinline__ void cpasync16(uint32_t saddr, const void* g) {
    asm volatile("cp.async.cg.shared.global [%0], [%1], 16;" :: "r"(saddr), "l"(g));
}
#define CP_COMMIT() asm volatile("cp.async.commit_group;" ::: "memory")
#define CP_WAIT(n)  asm volatile("cp.async.wait_group %0;" :: "n"(n) : "memory")

__device__ __forceinline__ void ldmat2(uint32_t* r, uint32_t a) {
    asm volatile("ldmatrix.sync.aligned.m8n8.x2.shared.b16 {%0,%1}, [%2];"
        : "=r"(r[0]), "=r"(r[1]) : "r"(a));
}
__device__ __forceinline__ void mma_f16(float* d, uint32_t a0, uint32_t a1,
                                        uint32_t a2, uint32_t a3,
                                        uint32_t b0, uint32_t b1) {
    asm volatile("mma.sync.aligned.m16n8k16.row.col.f32.f16.f16.f32 "
        "{%0,%1,%2,%3}, {%4,%5,%6,%7}, {%8,%9}, {%0,%1,%2,%3};"
        : "+f"(d[0]), "+f"(d[1]), "+f"(d[2]), "+f"(d[3])
        : "r"(a0), "r"(a1), "r"(a2), "r"(a3), "r"(b0), "r"(b1));
}
__device__ __forceinline__ uint32_t h2u(__half2 v) {
    return *reinterpret_cast<uint32_t*>(&v);
}

// ---------------- weight conversion: fp16 + mma-fragment packing -------------------
// Packed per layer (M x K): tile (tm, tk) of 128x64 = 8192 halfs; within,
// slot fs = mi*4 + ks in [0,32), lane in [0,32), j in [0,8):
//   packed[(((tm*(K/64)+tk)*32 + fs)*32 + lane)*8 + j]
//     = W[tm*128 + (fs>>2)*16 + (lane>>2) + ((j>>1)&1)*8]
//        [tk*64 + (fs&3)*16 + (lane&3)*2 + (j&1) + ((j>>2)&1)*8]
template<int GLU>
__global__ void convw_pack(const float* __restrict__ W, __half* __restrict__ o,
                           int M, int K, int n)
{
    int i = blockIdx.x * blockDim.x + threadIdx.x;
    if (i >= n) return;
    int per = M * K;
    int l = i / per;
    int e = i % per;
    int j    = e & 7;
    int lane = (e >> 3) & 31;
    int fs   = (e >> 8) & 31;          // 32 slots per 128x64 tile
    int tile = e >> 13;                // 8192 halfs per tile
    int ntK = K >> 6;
    int tk = tile % ntK, tm = tile / ntK;
    int mi = fs >> 2, ks = fs & 3;
    int r = tm*128 + mi*16 + (lane >> 2) + ((j >> 1) & 1)*8;
    int c = tk*64  + ks*16 + (lane & 3)*2 + (j & 1) + ((j >> 2) & 1)*8;
    int src_r = GLU ? ((r & 1) ? (M/2 + (r >> 1)) : (r >> 1)) : r;
    o[i] = __float2half(W[(size_t)l*per + (size_t)src_r*K + c]);
}

// ---------------- transposes ------------------------------------------------------
__global__ void transpose_in(const float* __restrict__ in, float* __restrict__ out)
{
    __shared__ float tile[32][33];
    int b = blockIdx.z, t0 = blockIdx.x*32, h0 = blockIdx.y*32;
    int tx = threadIdx.x, ty = threadIdx.y;
    #pragma unroll
    for (int i = 0; i < 4; ++i)
        tile[ty + i*8][tx] = in[((size_t)b*HH + h0 + ty + i*8)*TT + t0 + tx];
    __syncthreads();
    #pragma unroll
    for (int i = 0; i < 4; ++i)
        out[((size_t)b*TT + t0 + ty + i*8)*HH + h0 + tx] = tile[tx][ty + i*8];
}
__global__ void transpose_out(const float* __restrict__ in, const float* __restrict__ mask,
                              float* __restrict__ out)
{
    __shared__ float tile[32][33];
    int b = blockIdx.z, t0 = blockIdx.x*32, h0 = blockIdx.y*32;
    int tx = threadIdx.x, ty = threadIdx.y;
    #pragma unroll
    for (int i = 0; i < 4; ++i)
        tile[ty + i*8][tx] = in[((size_t)b*TT + t0 + ty + i*8)*HH + h0 + tx];
    __syncthreads();
    float mv = mask[(size_t)b*TT + t0 + tx];
    #pragma unroll
    for (int i = 0; i < 4; ++i)
        out[((size_t)b*HH + h0 + ty + i*8)*TT + t0 + tx] = tile[tx][ty + i*8] * mv;
}

// ---------------- S4D scan: coalesced smem-staged I/O, 8 h per block --------------
__global__ __launch_bounds__(256)
void scan_kernel(const float* __restrict__ x, const float* __restrict__ mask,
                 const float* __restrict__ log_dt,
                 const float* __restrict__ A_re, const float* __restrict__ A_im,
                 const float* __restrict__ C_re, const float* __restrict__ C_im,
                 const float* __restrict__ Dp,
                 __half* __restrict__ yt, int layer)
{
    __shared__ float sxT[32][9];
    __shared__ float syo[32][9];
    __shared__ float sc[8][32][33];
    int tid = threadIdx.x;
    int w = tid >> 5, lane = tid & 31;
    int gidx = blockIdx.x * 8;
    int b = gidx / HH, h0 = gidx % HH;
    int h = h0 + w;
    int lt = tid >> 3, lh = tid & 7;

    float dt = expf(log_dt[layer*HH + h]);
    int pidx = (layer*HH + h) * N2 + lane;
    float ar = A_re[pidx], ai = A_im[pidx];
    float dre = ar * dt, dim = ai * dt;
    float e   = expf(dre);
    float wre = e * cosf(dim);
    float wim = e * sinf(dim);
    float nre = wre - 1.0f, nim = wim;
    float d2  = ar*ar + ai*ai;
    float qre = (nre*ar + nim*ai) / d2;
    float qim = (nim*ar - nre*ai) / d2;
    float cre = C_re[pidx], cim = C_im[pidx];
    float cdre = cre*qre - cim*qim;
    float cdim = cre*qim + cim*qre;
    float Dv = Dp[layer*HH + h];

    float sre = 0.f, sim = 0.f;

    for (int c = 0; c < TT/32; ++c) {
        int t0 = c*32;
        float mval = mask[(size_t)b*TT + t0 + lt];
        sxT[lt][lh] = x[((size_t)b*TT + t0 + lt)*HH + h0 + lh] * mval;
        __syncthreads();

        #pragma unroll
        for (int j = 0; j < 32; ++j) {
            float xj = sxT[j][w];
            float tre = fmaf(wre, sre, fmaf(-wim, sim, xj));
            float tim = fmaf(wre, sim, wim * sre);
            sre = tre; sim = tim;
            sc[w][lane][j] = fmaf(cdre, sre, -cdim * sim);
        }
        __syncwarp();
        float sum = 0.f;
        #pragma unroll
        for (int n = 0; n < 32; ++n) sum += sc[w][n][lane];
        float yv = 2.0f*sum + Dv * sxT[lane][w];
        yv = 0.5f * yv * (1.0f + erff(yv * 0.70710678118654752f));
        syo[lane][w] = yv;
        __syncthreads();

        yt[((size_t)b*TT + t0 + lt)*HH + h0 + lh] = __float2half(syo[lt][lh]);
        __syncthreads();
    }
}

// ---------------- fp16 mma.sync GEMM: 128x256x64 tiles, 4-stage pipeline ----------
// A: fragment-packed 16KB tiles (linear). B: 128B rows (=64 fp16), XOR swizzle.
#define BM 128
#define BN 256
#define BK 64
#define ATILE 16384                 // 128x64 fp16 packed
#define BTILE 32768                 // 256 rows x 128B
#define STAGE (ATILE + BTILE)       // 48KB
#define NSTAGE 4
#define EPI_SMEM (256*132*4)        // 135168
#define GEMM_SMEM (NSTAGE*STAGE)    // 196608 > EPI_SMEM

#define EPI_GLU  0
#define EPI_F16  1
#define EPI_FP32 2

__device__ __forceinline__ void load_stage(
    uint32_t sbase,
    const __half* __restrict__ Wt, const __half* __restrict__ Xt,
    int K, int m0, size_t brow, int k0, int tid)
{
    // A: contiguous packed tile (8192 halfs = 1024 x 16B)
    const __half* Wp = Wt + ((size_t)(m0 >> 7) * (K >> 6) + (k0 >> 6)) * 8192;
    #pragma unroll
    for (int i = 0; i < 4; ++i) {
        int s = tid + i*256;
        cpasync16(sbase + (uint32_t)s*16, Wp + s*8);
    }
    // B: 256 t-rows x 64 fp16 (128B rows), 16B-chunk XOR swizzle (2048 x 16B)
    #pragma unroll
    for (int i = 0; i < 8; ++i) {
        int s = tid + i*256;
        int row = s >> 3, c = s & 7;
        uint32_t dst = sbase + ATILE + (uint32_t)row*128 + (uint32_t)((c ^ (row & 7)) << 4);
        cpasync16(dst, Xt + (brow + row)*K + k0 + c*8);
    }
}

template<int EPI>
__global__ __launch_bounds__(256, 1)
void gemm_mma(const __half* __restrict__ Wt, const __half* __restrict__ Xt,
              const float* __restrict__ bias, const float* __restrict__ mask,
              float* __restrict__ OutF, __half* __restrict__ OutH,
              int K, int ldo)
{
    extern __shared__ char smem[];
    uint32_t sb = smem_u32(smem);
    int tid = threadIdx.x;
    int b  = blockIdx.z;
    int m0 = blockIdx.y * BM;
    int t0 = blockIdx.x * BN;
    size_t brow = (size_t)b*TT + t0;

    int w = tid >> 5, lane = tid & 31;
    int wm = w & 1, wn = w >> 1;       // 2 M-halves x 4 N-quarters (64 cols each)

    float acc[4][8][4];
    #pragma unroll
    for (int i = 0; i < 4; ++i)
        #pragma unroll
        for (int j = 0; j < 8; ++j)
            #pragma unroll
            for (int q = 0; q < 4; ++q) acc[i][j][q] = 0.f;

    // B ldmatrix addressing: row = wn*64 + ni*8 + (lane&7); k-half by lane>>3.
    uint32_t rB7   = (uint32_t)(lane & 7);
    uint32_t half_ = (uint32_t)((lane >> 3) & 1);
    uint32_t bRow0 = (uint32_t)(wn*64 + (lane & 7)) * 128;
    // A packed: slot = (wm*4+mi)*4 + ks, 512B/slot, lane*16 within
    uint32_t aLane = (uint32_t)lane * 16;

    int nch = K / BK;
    load_stage(sb,           Wt, Xt, K, m0, brow, 0,    tid); CP_COMMIT();
    load_stage(sb +   STAGE, Wt, Xt, K, m0, brow, BK,   tid); CP_COMMIT();
    load_stage(sb + 2*STAGE, Wt, Xt, K, m0, brow, 2*BK, tid); CP_COMMIT();

    for (int ch = 0; ch < nch; ++ch) {
        CP_WAIT(2);
        __syncthreads();

        if (ch + 3 < nch)
            load_stage(sb + (uint32_t)((ch + 3) % NSTAGE) * STAGE,
                       Wt, Xt, K, m0, brow, (ch + 3) * BK, tid);
        CP_COMMIT();

        uint32_t cur = sb + (uint32_t)(ch % NSTAGE) * STAGE;
        const char* sA = smem + (cur - sb);
        uint32_t sB = cur + ATILE;

        #pragma unroll
        for (int ks = 0; ks < 4; ++ks) {
            uint32_t cx = (uint32_t)((((uint32_t)(ks*2) + half_) ^ rB7) << 4);

            uint32_t B01[8][2];
            #pragma unroll
            for (int ni = 0; ni < 8; ++ni)
                ldmat2(B01[ni], sB + bRow0 + (uint32_t)ni*1024 + cx);

            #pragma unroll
            for (int mi = 0; mi < 4; ++mi) {
                uint4 av = *(const uint4*)(sA + (uint32_t)(((wm*4 + mi)*4 + ks))*512 + aLane);
                #pragma unroll
                for (int ni = 0; ni < 8; ++ni)
                    mma_f16(acc[mi][ni], av.x, av.y, av.z, av.w, B01[ni][0], B01[ni][1]);
            }
        }
    }
    CP_WAIT(0);
    __syncthreads();   // mainloop done before smem reuse

    // ---- stage fragments to smem as [t][m] (132-float padded rows, 256 rows) ----
    float* smemf = (float*)smem;
    #pragma unroll
    for (int mi = 0; mi < 4; ++mi) {
        int ma = wm*64 + mi*16 + (lane >> 2);
        #pragma unroll
        for (int ni = 0; ni < 8; ++ni) {
            int tc = wn*64 + ni*8 + (lane & 3)*2;
            float* st = smemf + tc*132;
            st[ma]        = acc[mi][ni][0];
            st[132 + ma]  = acc[mi][ni][1];
            st[ma + 8]    = acc[mi][ni][2];
            st[132 + ma + 8] = acc[mi][ni][3];
        }
    }
    __syncthreads();

    // ---- write phase: coalesced channel-major output -------------------------
    if (EPI == EPI_GLU) {
        int m = lane*4;
        int r0 = m0 + m;
        float b0a = bias[(r0&1)?(HH+(r0>>1)):(r0>>1)];
        float b0g = bias[((r0+1)&1)?(HH+((r0+1)>>1)):((r0+1)>>1)];
        float b1a = bias[((r0+2)&1)?(HH+((r0+2)>>1)):((r0+2)>>1)];
        float b1g = bias[((r0+3)&1)?(HH+((r0+3)>>1)):((r0+3)>>1)];
        #pragma unroll
        for (int p = 0; p < 32; ++p) {
            int r = p*8 + (tid >> 5);
            float4 z = *(float4*)(smemf + r*132 + m);
            float a0 = z.x + b0a, gg0 = z.y + b0g;
            float a1 = z.z + b1a, gg1 = z.w + b1g;
            float2 s;
            s.x = a0 / (1.0f + expf(-gg0));
            s.y = a1 / (1.0f + expf(-gg1));
            *(float2*)(OutF + ((size_t)b*TT + t0 + r)*HH + (m0>>1) + lane*2) = s;
        }
    } else if (EPI == EPI_F16) {
        int m = lane*4;
        float4 bi = *(const float4*)(bias + m0 + m);
        #pragma unroll
        for (int p = 0; p < 32; ++p) {
            int r = p*8 + (tid >> 5);
            float mv = mask[(size_t)b*TT + t0 + r];
            float4 v = *(float4*)(smemf + r*132 + m);
            v.x = fmaxf(v.x + bi.x, 0.f) * mv;
            v.y = fmaxf(v.y + bi.y, 0.f) * mv;
            v.z = fmaxf(v.z + bi.z, 0.f) * mv;
            v.w = fmaxf(v.w + bi.w, 0.f) * mv;
            uint2 o;
            o.x = h2u(__floats2half2_rn(v.x, v.y));
            o.y = h2u(__floats2half2_rn(v.z, v.w));
            *(uint2*)(OutH + ((size_t)b*TT + t0 + r)*ldo + m0 + m) = o;
        }
    } else {
        int m = lane*4;
        float4 bi = *(const float4*)(bias + m0 + m);
        #pragma unroll
        for (int p = 0; p < 32; ++p) {
            int r = p*8 + (tid >> 5);
            float mv = mask[(size_t)b*TT + t0 + r];
            float4 v = *(float4*)(smemf + r*132 + m);
            v.x = (v.x + bi.x) * mv;
            v.y = (v.y + bi.y) * mv;
            v.z = (v.z + bi.z) * mv;
            v.w = (v.w + bi.w) * mv;
            *(float4*)(OutF + ((size_t)b*TT + t0 + r)*HH + m0 + m) = v;
        }
    }
}

// ---------------- channel LayerNorm (channels contiguous), warp per token ---------
template<int MODE>
__global__ __launch_bounds__(256)
void ln_kernel(const float* __restrict__ res, const float* __restrict__ yy,
               const float* __restrict__ mask,
               const float* __restrict__ gamma, const float* __restrict__ beta,
               float* __restrict__ outF, __half* __restrict__ outH)
{
    int g = blockIdx.x*8 + (threadIdx.x >> 5);
    int lane = threadIdx.x & 31;
    size_t base = (size_t)g*HH;
    float mv = mask[g];

    float4 v[3];
    float s = 0.f, q = 0.f;
    #pragma unroll
    for (int j = 0; j < 3; ++j) {
        float4 r1 = *(const float4*)(res + base + lane*4 + j*128);
        float4 r2 = *(const float4*)(yy  + base + lane*4 + j*128);
        float4 t;
        if (MODE == 0) {
            t.x = fmaf(r1.x, mv, r2.x); t.y = fmaf(r1.y, mv, r2.y);
            t.z = fmaf(r1.z, mv, r2.z); t.w = fmaf(r1.w, mv, r2.w);
        } else {
            t.x = r1.x + r2.x; t.y = r1.y + r2.y;
            t.z = r1.z + r2.z; t.w = r1.w + r2.w;
        }
        v[j] = t;
        s += t.x + t.y + t.z + t.w;
        q += t.x*t.x + t.y*t.y + t.z*t.z + t.w*t.w;
    }
    #pragma unroll
    for (int off = 16; off; off >>= 1) {
        s += __shfl_xor_sync(0xffffffffu, s, off);
        q += __shfl_xor_sync(0xffffffffu, q, off);
    }
    float mu = s * (1.0f/HH);
    float rs = rsqrtf(q * (1.0f/HH) - mu*mu + 1e-4f);

    #pragma unroll
    for (int j = 0; j < 3; ++j) {
        float4 ga = *(const float4*)(gamma + lane*4 + j*128);
        float4 be = *(const float4*)(beta  + lane*4 + j*128);
        float4 t = v[j];
        t.x = (t.x - mu)*rs*ga.x + be.x;
        t.y = (t.y - mu)*rs*ga.y + be.y;
        t.z = (t.z - mu)*rs*ga.z + be.z;
        t.w = (t.w - mu)*rs*ga.w + be.w;
        *(float4*)(outF + base + lane*4 + j*128) = t;
        if (MODE == 0) {
            uint2 o;
            o.x = h2u(__floats2half2_rn(t.x * mv, t.y * mv));
            o.y = h2u(__floats2half2_rn(t.z * mv, t.w * mv));
            *(uint2*)(outH + base + lane*4 + j*128) = o;
        }
    }
}

// ---------------- host launch -----------------------------------------------------
extern "C" void kernel_launch(void* const* d_in, const int* in_sizes, int n_in,
                              void* d_out, int out_size)
{
    (void)in_sizes; (void)n_in; (void)out_size;
    const float* x      = (const float*)d_in[0];
    const float* mask   = (const float*)d_in[1];
    const float* log_dt = (const float*)d_in[2];
    const float* A_re   = (const float*)d_in[3];
    const float* A_im   = (const float*)d_in[4];
    const float* C_re   = (const float*)d_in[5];
    const float* C_im   = (const float*)d_in[6];
    const float* Dp     = (const float*)d_in[7];
    const float* Wout   = (const float*)d_in[8];
    const float* bout   = (const float*)d_in[9];
    const float* g1     = (const float*)d_in[10];
    const float* be1    = (const float*)d_in[11];
    const float* W1     = (const float*)d_in[12];
    const float* bf1    = (const float*)d_in[13];
    const float* W2     = (const float*)d_in[14];
    const float* bf2    = (const float*)d_in[15];
    const float* g2     = (const float*)d_in[16];
    const float* be2    = (const float*)d_in[17];

    float *ga, *gb, *gc;
    __half *xt, *ht, *woutt, *w1t, *w2t;
    cudaGetSymbolAddress((void**)&ga, g_a);
    cudaGetSymbolAddress((void**)&gb, g_b);
    cudaGetSymbolAddress((void**)&gc, g_c);
    cudaGetSymbolAddress((void**)&xt, g_xt);
    cudaGetSymbolAddress((void**)&ht, g_ht);
    cudaGetSymbolAddress((void**)&woutt, g_woutt);
    cudaGetSymbolAddress((void**)&w1t, g_w1t);
    cudaGetSymbolAddress((void**)&w2t, g_w2t);

    cudaFuncSetAttribute(gemm_mma<EPI_GLU >, cudaFuncAttributeMaxDynamicSharedMemorySize, GEMM_SMEM);
    cudaFuncSetAttribute(gemm_mma<EPI_F16 >, cudaFuncAttributeMaxDynamicSharedMemorySize, GEMM_SMEM);
    cudaFuncSetAttribute(gemm_mma<EPI_FP32>, cudaFuncAttributeMaxDynamicSharedMemorySize, GEMM_SMEM);

    // weight conversion + fragment packing (all layers, once)
    convw_pack<1><<<(LYR*2*HH*HH + 255)/256, 256>>>(Wout, woutt, 2*HH, HH, LYR*2*HH*HH);
    convw_pack<0><<<(LYR*HF*HH   + 255)/256, 256>>>(W1,   w1t,   HF,   HH, LYR*HF*HH);
    convw_pack<0><<<(LYR*HH*HF   + 255)/256, 256>>>(W2,   w2t,   HH,   HF, LYR*HH*HF);

    // input to [B,T,H]
    transpose_in<<<dim3(TT/32, HH/32, BB), dim3(32, 8)>>>(x, ga);

    for (int l = 0; l < LYR; ++l) {
        scan_kernel<<<(BB*HH)/8, 256>>>(ga, mask, log_dt, A_re, A_im, C_re, C_im, Dp,
                                        xt, l);
        gemm_mma<EPI_GLU><<<dim3(TT/BN, (2*HH)/BM, BB), 256, GEMM_SMEM>>>(
            woutt + (size_t)l*2*HH*HH, xt, bout + (size_t)l*2*HH, mask,
            gb, nullptr, HH, 0);
        ln_kernel<0><<<NTOK/8, 256>>>(ga, gb, mask, g1 + (size_t)l*HH, be1 + (size_t)l*HH,
                                      gc, xt);
        gemm_mma<EPI_F16><<<dim3(TT/BN, HF/BM, BB), 256, GEMM_SMEM>>>(
            w1t + (size_t)l*HF*HH, xt, bf1 + (size_t)l*HF, mask,
            nullptr, ht, HH, HF);
        gemm_mma<EPI_FP32><<<dim3(TT/BN, HH/BM, BB), 256, GEMM_SMEM>>>(
            w2t + (size_t)l*HH*HF, ht, bf2 + (size_t)l*HH, mask,
            gb, nullptr, HF, 0);
        ln_kernel<1><<<NTOK/8, 256>>>(gc, gb, mask, g2 + (size_t)l*HH, be2 + (size_t)l*HH,
                                      ga, nullptr);
    }
    transpose_out<<<dim3(TT/32, HH/32, BB), dim3(32, 8)>>>(ga, mask, (float*)d_out);
}

// round 17
// speedup vs baseline: 1.1364x; 1.1364x over previous
#include <cuda_runtime.h>
#include <cuda_fp16.h>
#include <math.h>
#include <stdint.h>

#define LYR 6
#define BB  16
#define HH  384
#define TT  2048
#define N2  32
#define HF  1536
#define NTOK (BB*TT)

// ---------------- scratch (device globals) ----------------------------------------
__device__ float g_a[(size_t)NTOK*HH];    // xcur [B,T,H]
__device__ float g_c[(size_t)NTOK*HH];    // x1 (LN1 out, fp32 residual)
__device__ __half g_bh[(size_t)NTOK*HH];  // s4 / FFN out (fp16 intermediates)
__device__ __half g_xt[(size_t)NTOK*HH];  // fp16 K=384 operand [B,T,H]
__device__ __half g_ht[(size_t)NTOK*HF];  // fp16 K=1536 operand [B,T,HF]
__device__ __half g_woutt[LYR*2*HH*HH];   // GLU-permuted, fragment-packed fp16 weights
__device__ __half g_w1t[LYR*HF*HH];
__device__ __half g_w2t[LYR*HH*HF];

// ================= helpers =================
__device__ __forceinline__ uint32_t smem_u32(const void* p) {
    uint32_t a;
    asm("{ .reg .u64 t; cvta.to.shared.u64 t, %1; cvt.u32.u64 %0, t; }" : "=r"(a) : "l"(p));
    return a;
}
__device__ __forceinline__ void cpasync16(uint32_t saddr, const void* g) {
    asm volatile("cp.async.cg.shared.global [%0], [%1], 16;" :: "r"(saddr), "l"(g));
}
#define CP_COMMIT() asm volatile("cp.async.commit_group;" ::: "memory")
#define CP_WAIT(n)  asm volatile("cp.async.wait_group %0;" :: "n"(n) : "memory")

__device__ __forceinline__ void ldmat2(uint32_t* r, uint32_t a) {
    asm volatile("ldmatrix.sync.aligned.m8n8.x2.shared.b16 {%0,%1}, [%2];"
        : "=r"(r[0]), "=r"(r[1]) : "r"(a));
}
__device__ __forceinline__ void mma_f16(float* d, uint32_t a0, uint32_t a1,
                                        uint32_t a2, uint32_t a3,
                                        uint32_t b0, uint32_t b1) {
    asm volatile("mma.sync.aligned.m16n8k16.row.col.f32.f16.f16.f32 "
        "{%0,%1,%2,%3}, {%4,%5,%6,%7}, {%8,%9}, {%0,%1,%2,%3};"
        : "+f"(d[0]), "+f"(d[1]), "+f"(d[2]), "+f"(d[3])
        : "r"(a0), "r"(a1), "r"(a2), "r"(a3), "r"(b0), "r"(b1));
}
__device__ __forceinline__ uint32_t h2u(__half2 v) {
    return *reinterpret_cast<uint32_t*>(&v);
}
__device__ __forceinline__ __half2 u2h(uint32_t v) {
    return *reinterpret_cast<__half2*>(&v);
}

// ---------------- weight conversion: fp16 + mma-fragment packing -------------------
// Packed per layer (M x K): tile (tm, tk) of 128x64 = 8192 halfs; within,
// slot fs = mi*4 + ks in [0,32), lane in [0,32), j in [0,8):
//   packed[(((tm*(K/64)+tk)*32 + fs)*32 + lane)*8 + j]
//     = W[tm*128 + (fs>>2)*16 + (lane>>2) + ((j>>1)&1)*8]
//        [tk*64 + (fs&3)*16 + (lane&3)*2 + (j&1) + ((j>>2)&1)*8]
template<int GLU>
__global__ void convw_pack(const float* __restrict__ W, __half* __restrict__ o,
                           int M, int K, int n)
{
    int i = blockIdx.x * blockDim.x + threadIdx.x;
    if (i >= n) return;
    int per = M * K;
    int l = i / per;
    int e = i % per;
    int j    = e & 7;
    int lane = (e >> 3) & 31;
    int fs   = (e >> 8) & 31;
    int tile = e >> 13;
    int ntK = K >> 6;
    int tk = tile % ntK, tm = tile / ntK;
    int mi = fs >> 2, ks = fs & 3;
    int r = tm*128 + mi*16 + (lane >> 2) + ((j >> 1) & 1)*8;
    int c = tk*64  + ks*16 + (lane & 3)*2 + (j & 1) + ((j >> 2) & 1)*8;
    int src_r = GLU ? ((r & 1) ? (M/2 + (r >> 1)) : (r >> 1)) : r;
    o[i] = __float2half(W[(size_t)l*per + (size_t)src_r*K + c]);
}

// ---------------- transposes ------------------------------------------------------
__global__ void transpose_in(const float* __restrict__ in, float* __restrict__ out)
{
    __shared__ float tile[32][33];
    int b = blockIdx.z, t0 = blockIdx.x*32, h0 = blockIdx.y*32;
    int tx = threadIdx.x, ty = threadIdx.y;
    #pragma unroll
    for (int i = 0; i < 4; ++i)
        tile[ty + i*8][tx] = in[((size_t)b*HH + h0 + ty + i*8)*TT + t0 + tx];
    __syncthreads();
    #pragma unroll
    for (int i = 0; i < 4; ++i)
        out[((size_t)b*TT + t0 + ty + i*8)*HH + h0 + tx] = tile[tx][ty + i*8];
}
__global__ void transpose_out(const float* __restrict__ in, const float* __restrict__ mask,
                              float* __restrict__ out)
{
    __shared__ float tile[32][33];
    int b = blockIdx.z, t0 = blockIdx.x*32, h0 = blockIdx.y*32;
    int tx = threadIdx.x, ty = threadIdx.y;
    #pragma unroll
    for (int i = 0; i < 4; ++i)
        tile[ty + i*8][tx] = in[((size_t)b*TT + t0 + ty + i*8)*HH + h0 + tx];
    __syncthreads();
    float mv = mask[(size_t)b*TT + t0 + tx];
    #pragma unroll
    for (int i = 0; i < 4; ++i)
        out[((size_t)b*HH + h0 + ty + i*8)*TT + t0 + tx] = tile[tx][ty + i*8] * mv;
}

// ---------------- S4D scan: coalesced smem-staged I/O, 8 h per block --------------
__global__ __launch_bounds__(256)
void scan_kernel(const float* __restrict__ x, const float* __restrict__ mask,
                 const float* __restrict__ log_dt,
                 const float* __restrict__ A_re, const float* __restrict__ A_im,
                 const float* __restrict__ C_re, const float* __restrict__ C_im,
                 const float* __restrict__ Dp,
                 __half* __restrict__ yt, int layer)
{
    __shared__ float sxT[32][9];
    __shared__ float syo[32][9];
    __shared__ float sc[8][32][33];
    int tid = threadIdx.x;
    int w = tid >> 5, lane = tid & 31;
    int gidx = blockIdx.x * 8;
    int b = gidx / HH, h0 = gidx % HH;
    int h = h0 + w;
    int lt = tid >> 3, lh = tid & 7;

    float dt = expf(log_dt[layer*HH + h]);
    int pidx = (layer*HH + h) * N2 + lane;
    float ar = A_re[pidx], ai = A_im[pidx];
    float dre = ar * dt, dim = ai * dt;
    float e   = expf(dre);
    float wre = e * cosf(dim);
    float wim = e * sinf(dim);
    float nre = wre - 1.0f, nim = wim;
    float d2  = ar*ar + ai*ai;
    float qre = (nre*ar + nim*ai) / d2;
    float qim = (nim*ar - nre*ai) / d2;
    float cre = C_re[pidx], cim = C_im[pidx];
    float cdre = cre*qre - cim*qim;
    float cdim = cre*qim + cim*qre;
    float Dv = Dp[layer*HH + h];

    float sre = 0.f, sim = 0.f;

    for (int c = 0; c < TT/32; ++c) {
        int t0 = c*32;
        float mval = mask[(size_t)b*TT + t0 + lt];
        sxT[lt][lh] = x[((size_t)b*TT + t0 + lt)*HH + h0 + lh] * mval;
        __syncthreads();

        #pragma unroll
        for (int j = 0; j < 32; ++j) {
            float xj = sxT[j][w];
            float tre = fmaf(wre, sre, fmaf(-wim, sim, xj));
            float tim = fmaf(wre, sim, wim * sre);
            sre = tre; sim = tim;
            sc[w][lane][j] = fmaf(cdre, sre, -cdim * sim);
        }
        __syncwarp();
        float sum = 0.f;
        #pragma unroll
        for (int n = 0; n < 32; ++n) sum += sc[w][n][lane];
        float yv = 2.0f*sum + Dv * sxT[lane][w];
        yv = 0.5f * yv * (1.0f + erff(yv * 0.70710678118654752f));
        syo[lane][w] = yv;
        __syncthreads();

        yt[((size_t)b*TT + t0 + lt)*HH + h0 + lh] = __float2half(syo[lt][lh]);
        __syncthreads();
    }
}

// ---------------- fp16 mma.sync GEMM: 128x128x64 tiles, 3 stages, 2 CTAs/SM -------
// A: fragment-packed 16KB tiles (linear). B: 128B rows (=64 fp16), XOR swizzle.
#define BM 128
#define BN 128
#define BK 64
#define ATILE 16384                 // 128x64 fp16 packed
#define STAGE (2*ATILE)             // A + B = 32KB
#define NSTAGE 3
#define GEMM_SMEM (NSTAGE*STAGE)    // 98304; epilogue needs 128*132*4 = 67584

#define EPI_GLU   0
#define EPI_RELU  1
#define EPI_PLAIN 2

__device__ __forceinline__ void load_stage(
    uint32_t sbase,
    const __half* __restrict__ Wt, const __half* __restrict__ Xt,
    int K, int m0, size_t brow, int k0, int tid)
{
    const __half* Wp = Wt + ((size_t)(m0 >> 7) * (K >> 6) + (k0 >> 6)) * 8192;
    #pragma unroll
    for (int i = 0; i < 4; ++i) {
        int s = tid + i*256;
        cpasync16(sbase + (uint32_t)s*16, Wp + s*8);
    }
    #pragma unroll
    for (int i = 0; i < 4; ++i) {
        int s = tid + i*256;
        int row = s >> 3, c = s & 7;
        uint32_t dst = sbase + ATILE + (uint32_t)row*128 + (uint32_t)((c ^ (row & 7)) << 4);
        cpasync16(dst, Xt + (brow + row)*K + k0 + c*8);
    }
}

template<int EPI>
__global__ __launch_bounds__(256, 2)
void gemm_mma(const __half* __restrict__ Wt, const __half* __restrict__ Xt,
              const float* __restrict__ bias, const float* __restrict__ mask,
              __half* __restrict__ OutH, int K, int ldo)
{
    extern __shared__ char smem[];
    uint32_t sb = smem_u32(smem);
    int tid = threadIdx.x;
    int b  = blockIdx.z;
    int m0 = blockIdx.y * BM;
    int t0 = blockIdx.x * BN;
    size_t brow = (size_t)b*TT + t0;

    int w = tid >> 5, lane = tid & 31;
    int wm = w & 1, wn = w >> 1;

    float acc[4][4][4];
    #pragma unroll
    for (int i = 0; i < 4; ++i)
        #pragma unroll
        for (int j = 0; j < 4; ++j)
            #pragma unroll
            for (int q = 0; q < 4; ++q) acc[i][j][q] = 0.f;

    uint32_t rB7   = (uint32_t)(lane & 7);
    uint32_t half_ = (uint32_t)((lane >> 3) & 1);
    uint32_t bRow0 = (uint32_t)(wn*32 + (lane & 7)) * 128;
    uint32_t aLane = (uint32_t)lane * 16;

    int nch = K / BK;
    load_stage(sb,          Wt, Xt, K, m0, brow, 0,  tid);
    CP_COMMIT();
    load_stage(sb + STAGE,  Wt, Xt, K, m0, brow, BK, tid);
    CP_COMMIT();

    for (int ch = 0; ch < nch; ++ch) {
        CP_WAIT(1);
        __syncthreads();

        if (ch + 2 < nch)
            load_stage(sb + (uint32_t)((ch + 2) % NSTAGE) * STAGE,
                       Wt, Xt, K, m0, brow, (ch + 2) * BK, tid);
        CP_COMMIT();

        uint32_t cur = sb + (uint32_t)(ch % NSTAGE) * STAGE;
        const char* sA = smem + (cur - sb);
        uint32_t sB = cur + ATILE;

        #pragma unroll
        for (int ks = 0; ks < 4; ++ks) {
            uint32_t cx = (uint32_t)((((uint32_t)(ks*2) + half_) ^ rB7) << 4);

            uint32_t B01[4][2];
            #pragma unroll
            for (int ni = 0; ni < 4; ++ni)
                ldmat2(B01[ni], sB + bRow0 + (uint32_t)ni*1024 + cx);

            #pragma unroll
            for (int mi = 0; mi < 4; ++mi) {
                uint4 av = *(const uint4*)(sA + (uint32_t)(((wm*4 + mi)*4 + ks))*512 + aLane);
                #pragma unroll
                for (int ni = 0; ni < 4; ++ni)
                    mma_f16(acc[mi][ni], av.x, av.y, av.z, av.w, B01[ni][0], B01[ni][1]);
            }
        }
    }
    __syncthreads();   // mainloop done before smem reuse

    // ---- stage fragments to smem as [t][m] (132-float padded rows) ----
    float* smemf = (float*)smem;
    #pragma unroll
    for (int mi = 0; mi < 4; ++mi) {
        int ma = wm*64 + mi*16 + (lane >> 2);
        #pragma unroll
        for (int ni = 0; ni < 4; ++ni) {
            int tc = wn*32 + ni*8 + (lane & 3)*2;
            float* st = smemf + tc*132;
            st[ma]        = acc[mi][ni][0];
            st[132 + ma]  = acc[mi][ni][1];
            st[ma + 8]    = acc[mi][ni][2];
            st[132 + ma + 8] = acc[mi][ni][3];
        }
    }
    __syncthreads();

    // ---- write phase: coalesced channel-major fp16 output --------------------
    if (EPI == EPI_GLU) {
        int m = lane*4;
        int r0 = m0 + m;
        float b0a = bias[(r0&1)?(HH+(r0>>1)):(r0>>1)];
        float b0g = bias[((r0+1)&1)?(HH+((r0+1)>>1)):((r0+1)>>1)];
        float b1a = bias[((r0+2)&1)?(HH+((r0+2)>>1)):((r0+2)>>1)];
        float b1g = bias[((r0+3)&1)?(HH+((r0+3)>>1)):((r0+3)>>1)];
        #pragma unroll
        for (int p = 0; p < 16; ++p) {
            int r = p*8 + (tid >> 5);
            float4 z = *(float4*)(smemf + r*132 + m);
            float a0 = z.x + b0a, gg0 = z.y + b0g;
            float a1 = z.z + b1a, gg1 = z.w + b1g;
            float s0 = a0 / (1.0f + expf(-gg0));
            float s1 = a1 / (1.0f + expf(-gg1));
            *(uint32_t*)(OutH + ((size_t)b*TT + t0 + r)*HH + (m0>>1) + lane*2)
                = h2u(__floats2half2_rn(s0, s1));
        }
    } else {
        int m = lane*4;
        float4 bi = *(const float4*)(bias + m0 + m);
        #pragma unroll
        for (int p = 0; p < 16; ++p) {
            int r = p*8 + (tid >> 5);
            float mv = mask[(size_t)b*TT + t0 + r];
            float4 v = *(float4*)(smemf + r*132 + m);
            v.x = v.x + bi.x; v.y = v.y + bi.y;
            v.z = v.z + bi.z; v.w = v.w + bi.w;
            if (EPI == EPI_RELU) {
                v.x = fmaxf(v.x, 0.f); v.y = fmaxf(v.y, 0.f);
                v.z = fmaxf(v.z, 0.f); v.w = fmaxf(v.w, 0.f);
            }
            v.x *= mv; v.y *= mv; v.z *= mv; v.w *= mv;
            uint2 o;
            o.x = h2u(__floats2half2_rn(v.x, v.y));
            o.y = h2u(__floats2half2_rn(v.z, v.w));
            *(uint2*)(OutH + ((size_t)b*TT + t0 + r)*ldo + m0 + m) = o;
        }
    }
}

// ---------------- channel LayerNorm (channels contiguous), warp per token ---------
// yy is fp16 now. MODE 0: v = res*mask + yy; write x1 fp32 + fp16 (x1*mask)
//                 MODE 1: v = res + yy;      write fp32 only
template<int MODE>
__global__ __launch_bounds__(256)
void ln_kernel(const float* __restrict__ res, const __half* __restrict__ yy,
               const float* __restrict__ mask,
               const float* __restrict__ gamma, const float* __restrict__ beta,
               float* __restrict__ outF, __half* __restrict__ outH)
{
    int g = blockIdx.x*8 + (threadIdx.x >> 5);
    int lane = threadIdx.x & 31;
    size_t base = (size_t)g*HH;
    float mv = mask[g];

    float4 v[3];
    float s = 0.f, q = 0.f;
    #pragma unroll
    for (int j = 0; j < 3; ++j) {
        float4 r1 = *(const float4*)(res + base + lane*4 + j*128);
        uint2 raw = *(const uint2*)(yy + base + lane*4 + j*128);
        __half2 y0 = u2h(raw.x), y1 = u2h(raw.y);
        float4 r2;
        r2.x = __low2float(y0); r2.y = __high2float(y0);
        r2.z = __low2float(y1); r2.w = __high2float(y1);
        float4 t;
        if (MODE == 0) {
            t.x = fmaf(r1.x, mv, r2.x); t.y = fmaf(r1.y, mv, r2.y);
            t.z = fmaf(r1.z, mv, r2.z); t.w = fmaf(r1.w, mv, r2.w);
        } else {
            t.x = r1.x + r2.x; t.y = r1.y + r2.y;
            t.z = r1.z + r2.z; t.w = r1.w + r2.w;
        }
        v[j] = t;
        s += t.x + t.y + t.z + t.w;
        q += t.x*t.x + t.y*t.y + t.z*t.z + t.w*t.w;
    }
    #pragma unroll
    for (int off = 16; off; off >>= 1) {
        s += __shfl_xor_sync(0xffffffffu, s, off);
        q += __shfl_xor_sync(0xffffffffu, q, off);
    }
    float mu = s * (1.0f/HH);
    float rs = rsqrtf(q * (1.0f/HH) - mu*mu + 1e-4f);

    #pragma unroll
    for (int j = 0; j < 3; ++j) {
        float4 ga = *(const float4*)(gamma + lane*4 + j*128);
        float4 be = *(const float4*)(beta  + lane*4 + j*128);
        float4 t = v[j];
        t.x = (t.x - mu)*rs*ga.x + be.x;
        t.y = (t.y - mu)*rs*ga.y + be.y;
        t.z = (t.z - mu)*rs*ga.z + be.z;
        t.w = (t.w - mu)*rs*ga.w + be.w;
        *(float4*)(outF + base + lane*4 + j*128) = t;
        if (MODE == 0) {
            uint2 o;
            o.x = h2u(__floats2half2_rn(t.x * mv, t.y * mv));
            o.y = h2u(__floats2half2_rn(t.z * mv, t.w * mv));
            *(uint2*)(outH + base + lane*4 + j*128) = o;
        }
    }
}

// ---------------- host launch -----------------------------------------------------
extern "C" void kernel_launch(void* const* d_in, const int* in_sizes, int n_in,
                              void* d_out, int out_size)
{
    (void)in_sizes; (void)n_in; (void)out_size;
    const float* x      = (const float*)d_in[0];
    const float* mask   = (const float*)d_in[1];
    const float* log_dt = (const float*)d_in[2];
    const float* A_re   = (const float*)d_in[3];
    const float* A_im   = (const float*)d_in[4];
    const float* C_re   = (const float*)d_in[5];
    const float* C_im   = (const float*)d_in[6];
    const float* Dp     = (const float*)d_in[7];
    const float* Wout   = (const float*)d_in[8];
    const float* bout   = (const float*)d_in[9];
    const float* g1     = (const float*)d_in[10];
    const float* be1    = (const float*)d_in[11];
    const float* W1     = (const float*)d_in[12];
    const float* bf1    = (const float*)d_in[13];
    const float* W2     = (const float*)d_in[14];
    const float* bf2    = (const float*)d_in[15];
    const float* g2     = (const float*)d_in[16];
    const float* be2    = (const float*)d_in[17];

    float *ga, *gc;
    __half *gbh, *xt, *ht, *woutt, *w1t, *w2t;
    cudaGetSymbolAddress((void**)&ga, g_a);
    cudaGetSymbolAddress((void**)&gc, g_c);
    cudaGetSymbolAddress((void**)&gbh, g_bh);
    cudaGetSymbolAddress((void**)&xt, g_xt);
    cudaGetSymbolAddress((void**)&ht, g_ht);
    cudaGetSymbolAddress((void**)&woutt, g_woutt);
    cudaGetSymbolAddress((void**)&w1t, g_w1t);
    cudaGetSymbolAddress((void**)&w2t, g_w2t);

    cudaFuncSetAttribute(gemm_mma<EPI_GLU  >, cudaFuncAttributeMaxDynamicSharedMemorySize, GEMM_SMEM);
    cudaFuncSetAttribute(gemm_mma<EPI_RELU >, cudaFuncAttributeMaxDynamicSharedMemorySize, GEMM_SMEM);
    cudaFuncSetAttribute(gemm_mma<EPI_PLAIN>, cudaFuncAttributeMaxDynamicSharedMemorySize, GEMM_SMEM);

    // weight conversion + fragment packing (all layers, once)
    convw_pack<1><<<(LYR*2*HH*HH + 255)/256, 256>>>(Wout, woutt, 2*HH, HH, LYR*2*HH*HH);
    convw_pack<0><<<(LYR*HF*HH   + 255)/256, 256>>>(W1,   w1t,   HF,   HH, LYR*HF*HH);
    convw_pack<0><<<(LYR*HH*HF   + 255)/256, 256>>>(W2,   w2t,   HH,   HF, LYR*HH*HF);

    // input to [B,T,H]
    transpose_in<<<dim3(TT/32, HH/32, BB), dim3(32, 8)>>>(x, ga);

    for (int l = 0; l < LYR; ++l) {
        // 1. scan -> fp16 operand
        scan_kernel<<<(BB*HH)/8, 256>>>(ga, mask, log_dt, A_re, A_im, C_re, C_im, Dp,
                                        xt, l);
        // 2. Wout GEMM + fused GLU -> s4 fp16 (g_bh)
        gemm_mma<EPI_GLU><<<dim3(TT/BN, (2*HH)/BM, BB), 256, GEMM_SMEM>>>(
            woutt + (size_t)l*2*HH*HH, xt, bout + (size_t)l*2*HH, mask, gbh, HH, 0);
        // 3. LN1 -> x1 fp32 (g_c) + fp16 operand
        ln_kernel<0><<<NTOK/8, 256>>>(ga, gbh, mask, g1 + (size_t)l*HH, be1 + (size_t)l*HH,
                                      gc, xt);
        // 4. W1 GEMM + relu + mask -> fp16 hidden [B,T,HF]
        gemm_mma<EPI_RELU><<<dim3(TT/BN, HF/BM, BB), 256, GEMM_SMEM>>>(
            w1t + (size_t)l*HF*HH, xt, bf1 + (size_t)l*HF, mask, ht, HH, HF);
        // 5. W2 GEMM + mask -> ffn out fp16 (g_bh)
        gemm_mma<EPI_PLAIN><<<dim3(TT/BN, HH/BM, BB), 256, GEMM_SMEM>>>(
            w2t + (size_t)l*HH*HF, ht, bf2 + (size_t)l*HH, mask, gbh, HF, HH);
        // 6. LN2 -> next x fp32 (g_a)
        ln_kernel<1><<<NTOK/8, 256>>>(gc, gbh, mask, g2 + (size_t)l*HH, be2 + (size_t)l*HH,
                                      ga, nullptr);
    }
    transpose_out<<<dim3(TT/32, HH/32, BB), dim3(32, 8)>>>(ga, mask, (float*)d_out);
}